// round 13
// baseline (speedup 1.0000x reference)
#include <cuda_runtime.h>
#include <cuda_fp16.h>
#include <cstdint>

// VectorQuantizer via mma.sync.m16n8k16 fp16 3-term split (emulated fp32 GEMM):
// x' = x*2^10 = h1+h2 (fp16), e' = e*2^14 = g1+g2 (fp16);
// mm*2^24 = h1g1 + h1g2 + h2g1 accumulated in fp32.
// R12: 4-stage cp.async ring (1 barrier/chunk), per-ntp B loads (low reg
// pressure), u-interleaved MMA order (dep distance 2), exact 2^-23 fold.
// encodings [32,64,64,64] f32 (B,D,H,W), codebook [64,512] f32.

#define Dv 64
#define Kv 512
#define HW 4096
#define MB 128
#define THREADS 256
#define NCH 64                  // codewords per chunk
#define NCHUNKS (Kv / NCH)      // 8

#define XSCALE 1024.0f          // 2^10
#define ESCALE 16384.0f         // 2^14
#define INVSC2 1.1920928955078125e-7f   // 2^-23, exact: fl(acc*2^-23) == 2*fl(acc*2^-24)

// ---- smem layout (bytes) ----
#define SA      0               // 2 x [128 rows][128B] fp16 A splits (swizzled)
#define SBB(p)  (32768 + (p) * 16384)   // 4-stage ring: 2 x [64 rows][128B] each
#define SEE     98304           // f32[512]
#define SXX     100352          // f32[128]
#define SBJ     100864          // i32[128]
#define SMTOT   101376

__device__ unsigned g_pack[2][Kv * 32];   // fp16 pairs, [split][j][d2], k-major
__device__ float    g_ee[Kv];

__device__ __forceinline__ void split2(float v, unsigned short& a, unsigned short& b) {
    __half h1 = __float2half_rn(v);
    float r1 = v - __half2float(h1);
    __half h2 = __float2half_rn(r1);
    a = __half_as_ushort(h1);
    b = __half_as_ushort(h2);
}

// ---- kernel 1: split codebook (scaled) + codeword norms (unscaled) ----
__global__ void __launch_bounds__(512) split_cb_kernel(const float* __restrict__ cb) {
    int j = threadIdx.x;
    float e = 0.0f;
#pragma unroll 4
    for (int d2 = 0; d2 < 32; d2++) {
        float c0 = cb[(2 * d2 + 0) * Kv + j];
        float c1 = cb[(2 * d2 + 1) * Kv + j];
        e = fmaf(c0, c0, e);
        e = fmaf(c1, c1, e);                 // sequential-d: validated ee channel
        unsigned short a0, b0, a1, b1;
        split2(c0 * ESCALE, a0, b0);         // exact power-of-2 scale
        split2(c1 * ESCALE, a1, b1);
        g_pack[0][j * 32 + d2] = (unsigned)a0 | ((unsigned)a1 << 16);
        g_pack[1][j * 32 + d2] = (unsigned)b0 | ((unsigned)b1 << 16);
    }
    g_ee[j] = e;
}

#define LDSM_X4(R, addr)                                                     \
    asm volatile("ldmatrix.sync.aligned.m8n8.x4.shared.b16 {%0,%1,%2,%3}, [%4];" \
                 : "=r"((R)[0]), "=r"((R)[1]), "=r"((R)[2]), "=r"((R)[3])    \
                 : "r"(addr))
#define MMA(C, A, B)                                                         \
    asm volatile("mma.sync.aligned.m16n8k16.row.col.f32.f16.f16.f32 "        \
                 "{%0,%1,%2,%3},{%4,%5,%6,%7},{%8,%9},{%0,%1,%2,%3};"        \
                 : "+f"((C)[0]), "+f"((C)[1]), "+f"((C)[2]), "+f"((C)[3])    \
                 : "r"((A)[0]), "r"((A)[1]), "r"((A)[2]), "r"((A)[3]),       \
                   "r"((B)[0]), "r"((B)[1]))

__device__ __forceinline__ void cp_async16(unsigned saddr, const void* gptr) {
    unsigned long long g = (unsigned long long)__cvta_generic_to_global((void*)gptr);
    asm volatile("cp.async.cg.shared.global [%0], [%1], 16;" :: "r"(saddr), "l"(g));
}
#define CP_COMMIT() asm volatile("cp.async.commit_group;")
#define CP_WAIT2()  asm volatile("cp.async.wait_group 2;")

extern __shared__ char smem[];

// Issue cp.async for one B chunk into ring buffer p (1024 x 16B; 4 per thread).
__device__ __forceinline__ void stage_b_async(unsigned sb, int ch, int p, int tid) {
#pragma unroll
    for (int it = 0; it < 4; it++) {
        int i = it * THREADS + tid;
        int s = i >> 9, r = i & 511;
        int jl = r >> 3, g = r & 7;
        unsigned dst = sb + SBB(p) + s * 8192 + jl * 128
                     + (((g ^ (jl & 7)) & 7) << 4);
        cp_async16(dst, &g_pack[s][(ch * NCH + jl) * 32 + g * 4]);
    }
}

// ---- kernel 2: fused split-GEMM + argmin + gather ----
__global__ void __launch_bounds__(THREADS, 2)
vq_mma_kernel(const float* __restrict__ enc, const float* __restrict__ cb,
              float* __restrict__ out) {
    unsigned sb;
    asm("{ .reg .u64 t; cvta.to.shared.u64 t, %1; cvt.u32.u64 %0, t; }"
        : "=r"(sb) : "l"(smem));
    const int tid  = threadIdx.x;
    const int wid  = tid >> 5;
    const int lane = tid & 31;

    const long long row0 = (long long)blockIdx.x * MB;
    const int b   = (int)(row0 >> 12);
    const int hw0 = (int)(row0 & 4095);
    const float* encb = enc + (long long)b * (Dv * HW) + hw0;

    float* eesh = (float*)(smem + SEE);
    float* xxsh = (float*)(smem + SXX);
    int*   bjsh = (int*)(smem + SBJ);

    // ---- prologue: kick off B chunks 0,1,2 into ring buffers 0,1,2 ----
    stage_b_async(sb, 0, 0, tid); CP_COMMIT();
    stage_b_async(sb, 1, 1, tid); CP_COMMIT();
    stage_b_async(sb, 2, 2, tid); CP_COMMIT();

    // ---- stage A: split scaled x tile into 2 swizzled fp16 tiles [128][64] ----
    for (int i = tid; i < 32 * MB; i += THREADS) {
        int d2 = i >> 7, m = i & 127;
        float v0 = encb[(2 * d2 + 0) * HW + m] * XSCALE;
        float v1 = encb[(2 * d2 + 1) * HW + m] * XSCALE;
        unsigned short a0, b0, a1, b1;
        split2(v0, a0, b0);
        split2(v1, a1, b1);
        unsigned off = (unsigned)(m * 128 + (((d2 >> 2) ^ (m & 7)) << 4) + ((d2 & 3) << 2));
        *(unsigned*)(smem + SA +     0 + off) = (unsigned)a0 | ((unsigned)a1 << 16);
        *(unsigned*)(smem + SA + 16384 + off) = (unsigned)b0 | ((unsigned)b1 << 16);
    }
    eesh[tid]       = g_ee[tid];
    eesh[tid + 256] = g_ee[tid + 256];
    if (tid < MB) {      // row norms, sequential-d fmaf (validated channel), unscaled
        float v = 0.0f;
#pragma unroll 8
        for (int d = 0; d < Dv; d++) { float a = encb[d * HW + tid]; v = fmaf(a, a, v); }
        xxsh[tid] = v;
    }
    __syncthreads();

    const int r0 = lane >> 2;         // 0..7 (row within half-stripe)
    const int wr = wid * 16;          // warp row base within block

    // ---- hoist all A fragments (chunk-invariant): afr[ks][split][4] ----
    const int rowA = wr + (lane & 15);       // warp's own 16-row stripe
    const int tA   = lane >> 4;
    unsigned afr[4][2][4];
#pragma unroll
    for (int ks = 0; ks < 4; ks++) {
        const unsigned chA = (unsigned)(ks * 2 + tA);
#pragma unroll
        for (int s = 0; s < 2; s++) {
            unsigned addrA = sb + SA + s * 16384 + rowA * 128
                           + (((chA ^ (rowA & 7)) & 7) << 4);
            LDSM_X4(afr[ks][s], addrA);
        }
    }
    const float xx0 = xxsh[wr + r0];
    const float xx1 = xxsh[wr + r0 + 8];

    float best0 = 3.4028235e38f, best1 = 3.4028235e38f;
    int   bj0 = 0, bj1 = 0;

    // B x4 lane geometry: lanes 0-15 -> n-tile 2*ntp, 16-31 -> 2*ntp+1
    const int rBbase = (lane >> 4) * 8 + (lane & 7);
    const int tB     = (lane >> 3) & 1;

    for (int ch = 0; ch < NCHUNKS; ch++) {
        CP_WAIT2();        // pending {ch,ch+1,ch+2} -> group ch complete
        __syncthreads();   // chunk ch visible; all warps done reading buf (ch+3)&3
        if (ch + 3 < NCHUNKS) stage_b_async(sb, ch + 3, (ch + 3) & 3, tid);
        CP_COMMIT();       // (possibly empty) keeps pending-group invariant at 3

        const unsigned bbuf = sb + SBB(ch & 3);

        float acc[8][4];
#pragma unroll
        for (int nt = 0; nt < 8; nt++)
#pragma unroll
            for (int q = 0; q < 4; q++) acc[nt][q] = 0.0f;

#pragma unroll
        for (int ks = 0; ks < 4; ks++) {
            const unsigned chB = (unsigned)(ks * 2 + tB);
#pragma unroll
            for (int ntp = 0; ntp < 4; ntp++) {
                const int rB = ntp * 16 + rBbase;
                unsigned bb[2][4];
#pragma unroll
                for (int s = 0; s < 2; s++) {
                    unsigned addrB = bbuf + s * 8192 + rB * 128
                                   + (((chB ^ (rB & 7)) & 7) << 4);
                    LDSM_X4(bb[s], addrB);
                }
                // u-interleaved: consecutive MMAs alternate accumulators
                // (dep distance 2); per-acc order h1g1,h1g2,h2g1 preserved.
                float* c0 = acc[2 * ntp + 0];
                float* c1 = acc[2 * ntp + 1];
                MMA(c0, afr[ks][0], bb[0] + 0);   // h1g1 u0
                MMA(c1, afr[ks][0], bb[0] + 2);   // h1g1 u1
                MMA(c0, afr[ks][0], bb[1] + 0);   // h1g2 u0
                MMA(c1, afr[ks][0], bb[1] + 2);   // h1g2 u1
                MMA(c0, afr[ks][1], bb[0] + 0);   // h2g1 u0
                MMA(c1, afr[ks][1], bb[0] + 2);   // h2g1 u1
            }
        }

        // ---- fold chunk into running argmin ----
        // t = fl(acc*2^-23) == fl(2*fl(acc*2^-24)) exactly; dist = fl(fl(xx-t)+ee)
        const int nb = ch * NCH + (lane & 3) * 2;
#pragma unroll
        for (int nt = 0; nt < 8; nt++) {
            const int n0 = nb + nt * 8;
            const float e0 = eesh[n0], e1 = eesh[n0 + 1];
            float t00 = __fmul_rn(acc[nt][0], INVSC2);
            float t01 = __fmul_rn(acc[nt][1], INVSC2);
            float t10 = __fmul_rn(acc[nt][2], INVSC2);
            float t11 = __fmul_rn(acc[nt][3], INVSC2);
            float d00 = __fadd_rn(__fsub_rn(xx0, t00), e0);
            float d01 = __fadd_rn(__fsub_rn(xx0, t01), e1);
            float d10 = __fadd_rn(__fsub_rn(xx1, t10), e0);
            float d11 = __fadd_rn(__fsub_rn(xx1, t11), e1);
            if (d00 < best0) { best0 = d00; bj0 = n0; }
            if (d01 < best0) { best0 = d01; bj0 = n0 + 1; }
            if (d10 < best1) { best1 = d10; bj1 = n0; }
            if (d11 < best1) { best1 = d11; bj1 = n0 + 1; }
        }
    }

    // ---- reduce argmin within each quad of lanes sharing a row ----
#pragma unroll
    for (int off = 1; off < 4; off <<= 1) {
        float od0 = __shfl_xor_sync(0xffffffffu, best0, off);
        int   oj0 = __shfl_xor_sync(0xffffffffu, bj0,   off);
        float od1 = __shfl_xor_sync(0xffffffffu, best1, off);
        int   oj1 = __shfl_xor_sync(0xffffffffu, bj1,   off);
        if (od0 < best0 || (od0 == best0 && oj0 < bj0)) { best0 = od0; bj0 = oj0; }
        if (od1 < best1 || (od1 == best1 && oj1 < bj1)) { best1 = od1; bj1 = oj1; }
    }
    if ((lane & 3) == 0) {
        bjsh[wr + r0]     = bj0;
        bjsh[wr + r0 + 8] = bj1;
    }
    __syncthreads();

    // ---- gather winning codeword, write [B,D,H,W] coalesced ----
    {
        float* outb = out + (long long)b * (Dv * HW) + hw0;
        const int r  = tid & 127;
        const int d0 = (tid >> 7) * 32;
        const int myj = bjsh[r];
#pragma unroll 8
        for (int d = d0; d < d0 + 32; d++)
            outb[d * HW + r] = __ldg(&cb[d * Kv + myj]);
    }
}

extern "C" void kernel_launch(void* const* d_in, const int* in_sizes, int n_in,
                              void* d_out, int out_size) {
    const float* enc = (const float*)d_in[0];   // [32,64,64,64]
    const float* cb  = (const float*)d_in[1];   // [64,512]
    float* out = (float*)d_out;

    cudaFuncSetAttribute(vq_mma_kernel, cudaFuncAttributeMaxDynamicSharedMemorySize, SMTOT);

    split_cb_kernel<<<1, 512>>>(cb);
    const long long n_rows = (long long)out_size / Dv;    // 131072
    const int blocks = (int)(n_rows / MB);                // 1024
    vq_mma_kernel<<<blocks, THREADS, SMTOT>>>(enc, cb, out);
}

// round 14
// speedup vs baseline: 1.0523x; 1.0523x over previous
#include <cuda_runtime.h>
#include <cuda_fp16.h>
#include <cstdint>

// VectorQuantizer via mma.sync.m16n8k16 fp16 3-term split (emulated fp32 GEMM):
// x' = x*2^10 = h1+h2 (fp16), e' = e*2^14 = g1+g2 (fp16);
// mm*2^24 = h1g1 + h1g2 + h2g1 accumulated in fp32.
// R14: R10 structure (2-buffer cp.async, per-ntp B, sequential MMA order) +
// 3 blocks/SM via launch_bounds(256,3): A frags de-hoisted (per-ks loads) to
// fit ~84 regs; exact 2^-23 fold.
// encodings [32,64,64,64] f32 (B,D,H,W), codebook [64,512] f32.

#define Dv 64
#define Kv 512
#define HW 4096
#define MB 128
#define THREADS 256
#define NCH 64                  // codewords per chunk
#define NCHUNKS (Kv / NCH)      // 8

#define XSCALE 1024.0f          // 2^10
#define ESCALE 16384.0f         // 2^14
#define INVSC2 1.1920928955078125e-7f   // 2^-23, exact: fl(acc*2^-23) == 2*fl(acc*2^-24)

// ---- smem layout (bytes) ----
#define SA      0               // 2 x [128 rows][128B] fp16 A splits (swizzled)
#define SBB(p)  (32768 + (p) * 16384)   // 2 x (2 x [64 rows][128B]) B splits
#define SEE     65536           // f32[512]
#define SXX     67584           // f32[128]
#define SBJ     68096           // i32[128]
#define SMTOT   68608

__device__ unsigned g_pack[2][Kv * 32];   // fp16 pairs, [split][j][d2], k-major
__device__ float    g_ee[Kv];

__device__ __forceinline__ void split2(float v, unsigned short& a, unsigned short& b) {
    __half h1 = __float2half_rn(v);
    float r1 = v - __half2float(h1);
    __half h2 = __float2half_rn(r1);
    a = __half_as_ushort(h1);
    b = __half_as_ushort(h2);
}

// ---- kernel 1: split codebook (scaled) + codeword norms (unscaled) ----
__global__ void __launch_bounds__(512) split_cb_kernel(const float* __restrict__ cb) {
    int j = threadIdx.x;
    float e = 0.0f;
#pragma unroll 4
    for (int d2 = 0; d2 < 32; d2++) {
        float c0 = cb[(2 * d2 + 0) * Kv + j];
        float c1 = cb[(2 * d2 + 1) * Kv + j];
        e = fmaf(c0, c0, e);
        e = fmaf(c1, c1, e);                 // sequential-d: validated ee channel
        unsigned short a0, b0, a1, b1;
        split2(c0 * ESCALE, a0, b0);         // exact power-of-2 scale
        split2(c1 * ESCALE, a1, b1);
        g_pack[0][j * 32 + d2] = (unsigned)a0 | ((unsigned)a1 << 16);
        g_pack[1][j * 32 + d2] = (unsigned)b0 | ((unsigned)b1 << 16);
    }
    g_ee[j] = e;
}

#define LDSM_X4(R, addr)                                                     \
    asm volatile("ldmatrix.sync.aligned.m8n8.x4.shared.b16 {%0,%1,%2,%3}, [%4];" \
                 : "=r"((R)[0]), "=r"((R)[1]), "=r"((R)[2]), "=r"((R)[3])    \
                 : "r"(addr))
#define MMA(C, A, B)                                                         \
    asm volatile("mma.sync.aligned.m16n8k16.row.col.f32.f16.f16.f32 "        \
                 "{%0,%1,%2,%3},{%4,%5,%6,%7},{%8,%9},{%0,%1,%2,%3};"        \
                 : "+f"((C)[0]), "+f"((C)[1]), "+f"((C)[2]), "+f"((C)[3])    \
                 : "r"((A)[0]), "r"((A)[1]), "r"((A)[2]), "r"((A)[3]),       \
                   "r"((B)[0]), "r"((B)[1]))

__device__ __forceinline__ void cp_async16(unsigned saddr, const void* gptr) {
    unsigned long long g = (unsigned long long)__cvta_generic_to_global((void*)gptr);
    asm volatile("cp.async.cg.shared.global [%0], [%1], 16;" :: "r"(saddr), "l"(g));
}
#define CP_COMMIT() asm volatile("cp.async.commit_group;")
#define CP_WAIT1()  asm volatile("cp.async.wait_group 1;")
#define CP_WAIT0()  asm volatile("cp.async.wait_group 0;")

extern __shared__ char smem[];

// Issue cp.async for one B chunk into buffer p (1024 x 16B; 4 per thread).
__device__ __forceinline__ void stage_b_async(unsigned sb, int ch, int p, int tid) {
#pragma unroll
    for (int it = 0; it < 4; it++) {
        int i = it * THREADS + tid;
        int s = i >> 9, r = i & 511;
        int jl = r >> 3, g = r & 7;
        unsigned dst = sb + SBB(p) + s * 8192 + jl * 128
                     + (((g ^ (jl & 7)) & 7) << 4);
        cp_async16(dst, &g_pack[s][(ch * NCH + jl) * 32 + g * 4]);
    }
    CP_COMMIT();
}

// ---- kernel 2: fused split-GEMM + argmin + gather ----
__global__ void __launch_bounds__(THREADS, 3)
vq_mma_kernel(const float* __restrict__ enc, const float* __restrict__ cb,
              float* __restrict__ out) {
    unsigned sb;
    asm("{ .reg .u64 t; cvta.to.shared.u64 t, %1; cvt.u32.u64 %0, t; }"
        : "=r"(sb) : "l"(smem));
    const int tid  = threadIdx.x;
    const int wid  = tid >> 5;
    const int lane = tid & 31;

    const long long row0 = (long long)blockIdx.x * MB;
    const int b   = (int)(row0 >> 12);
    const int hw0 = (int)(row0 & 4095);
    const float* encb = enc + (long long)b * (Dv * HW) + hw0;

    float* eesh = (float*)(smem + SEE);
    float* xxsh = (float*)(smem + SXX);
    int*   bjsh = (int*)(smem + SBJ);

    // ---- kick off B chunk 0 copy immediately ----
    stage_b_async(sb, 0, 0, tid);

    // ---- stage A: split scaled x tile into 2 swizzled fp16 tiles [128][64] ----
    for (int i = tid; i < 32 * MB; i += THREADS) {
        int d2 = i >> 7, m = i & 127;
        float v0 = encb[(2 * d2 + 0) * HW + m] * XSCALE;
        float v1 = encb[(2 * d2 + 1) * HW + m] * XSCALE;
        unsigned short a0, b0, a1, b1;
        split2(v0, a0, b0);
        split2(v1, a1, b1);
        unsigned off = (unsigned)(m * 128 + (((d2 >> 2) ^ (m & 7)) << 4) + ((d2 & 3) << 2));
        *(unsigned*)(smem + SA +     0 + off) = (unsigned)a0 | ((unsigned)a1 << 16);
        *(unsigned*)(smem + SA + 16384 + off) = (unsigned)b0 | ((unsigned)b1 << 16);
    }
    eesh[tid]       = g_ee[tid];
    eesh[tid + 256] = g_ee[tid + 256];
    if (tid < MB) {      // row norms, sequential-d fmaf (validated channel), unscaled
        float v = 0.0f;
#pragma unroll 8
        for (int d = 0; d < Dv; d++) { float a = encb[d * HW + tid]; v = fmaf(a, a, v); }
        xxsh[tid] = v;
    }
    __syncthreads();

    const int r0 = lane >> 2;         // 0..7 (row within half-stripe)
    const int wr = wid * 16;          // warp row base within block

    const int rowA = wr + (lane & 15);       // warp's own 16-row stripe
    const int tA   = lane >> 4;
    const float xx0 = xxsh[wr + r0];
    const float xx1 = xxsh[wr + r0 + 8];

    float best0 = 3.4028235e38f, best1 = 3.4028235e38f;
    int   bj0 = 0, bj1 = 0;

    // B x4 lane geometry: lanes 0-15 -> n-tile 2*ntp, 16-31 -> 2*ntp+1
    const int rBbase = (lane >> 4) * 8 + (lane & 7);
    const int tB     = (lane >> 3) & 1;

    for (int ch = 0; ch < NCHUNKS; ch++) {
        __syncthreads();   // all warps done reading the buffer being overwritten
        if (ch + 1 < NCHUNKS) {
            stage_b_async(sb, ch + 1, (ch + 1) & 1, tid);
            CP_WAIT1();    // chunk ch's group complete
        } else {
            CP_WAIT0();
        }
        __syncthreads();   // chunk ch data visible to all warps

        const unsigned bbuf = sb + SBB(ch & 1);

        float acc[8][4];
#pragma unroll
        for (int nt = 0; nt < 8; nt++)
#pragma unroll
            for (int q = 0; q < 4; q++) acc[nt][q] = 0.0f;

#pragma unroll
        for (int ks = 0; ks < 4; ks++) {
            // A fragments loaded per ks (de-hoisted to fit 3 blocks/SM)
            unsigned a[2][4];
            const unsigned chA = (unsigned)(ks * 2 + tA);
#pragma unroll
            for (int s = 0; s < 2; s++) {
                unsigned addrA = sb + SA + s * 16384 + rowA * 128
                               + (((chA ^ (rowA & 7)) & 7) << 4);
                LDSM_X4(a[s], addrA);
            }
            const unsigned chB = (unsigned)(ks * 2 + tB);
#pragma unroll
            for (int ntp = 0; ntp < 4; ntp++) {
                const int rB = ntp * 16 + rBbase;
                unsigned bb[2][4];
#pragma unroll
                for (int s = 0; s < 2; s++) {
                    unsigned addrB = bbuf + s * 8192 + rB * 128
                                   + (((chB ^ (rB & 7)) & 7) << 4);
                    LDSM_X4(bb[s], addrB);
                }
#pragma unroll
                for (int u = 0; u < 2; u++) {
                    const int nt = 2 * ntp + u;
                    MMA(acc[nt], a[0], bb[0] + 2 * u);   // h1g1
                    MMA(acc[nt], a[0], bb[1] + 2 * u);   // h1g2
                    MMA(acc[nt], a[1], bb[0] + 2 * u);   // h2g1
                }
            }
        }

        // ---- fold chunk into running argmin ----
        // t = fl(acc*2^-23) == fl(2*fl(acc*2^-24)) exactly; dist = fl(fl(xx-t)+ee)
        const int nb = ch * NCH + (lane & 3) * 2;
#pragma unroll
        for (int nt = 0; nt < 8; nt++) {
            const int n0 = nb + nt * 8;
            const float e0 = eesh[n0], e1 = eesh[n0 + 1];
            float t00 = __fmul_rn(acc[nt][0], INVSC2);
            float t01 = __fmul_rn(acc[nt][1], INVSC2);
            float t10 = __fmul_rn(acc[nt][2], INVSC2);
            float t11 = __fmul_rn(acc[nt][3], INVSC2);
            float d00 = __fadd_rn(__fsub_rn(xx0, t00), e0);
            float d01 = __fadd_rn(__fsub_rn(xx0, t01), e1);
            float d10 = __fadd_rn(__fsub_rn(xx1, t10), e0);
            float d11 = __fadd_rn(__fsub_rn(xx1, t11), e1);
            if (d00 < best0) { best0 = d00; bj0 = n0; }
            if (d01 < best0) { best0 = d01; bj0 = n0 + 1; }
            if (d10 < best1) { best1 = d10; bj1 = n0; }
            if (d11 < best1) { best1 = d11; bj1 = n0 + 1; }
        }
    }

    // ---- reduce argmin within each quad of lanes sharing a row ----
#pragma unroll
    for (int off = 1; off < 4; off <<= 1) {
        float od0 = __shfl_xor_sync(0xffffffffu, best0, off);
        int   oj0 = __shfl_xor_sync(0xffffffffu, bj0,   off);
        float od1 = __shfl_xor_sync(0xffffffffu, best1, off);
        int   oj1 = __shfl_xor_sync(0xffffffffu, bj1,   off);
        if (od0 < best0 || (od0 == best0 && oj0 < bj0)) { best0 = od0; bj0 = oj0; }
        if (od1 < best1 || (od1 == best1 && oj1 < bj1)) { best1 = od1; bj1 = oj1; }
    }
    if ((lane & 3) == 0) {
        bjsh[wr + r0]     = bj0;
        bjsh[wr + r0 + 8] = bj1;
    }
    __syncthreads();

    // ---- gather winning codeword, write [B,D,H,W] coalesced ----
    {
        float* outb = out + (long long)b * (Dv * HW) + hw0;
        const int r  = tid & 127;
        const int d0 = (tid >> 7) * 32;
        const int myj = bjsh[r];
#pragma unroll 8
        for (int d = d0; d < d0 + 32; d++)
            outb[d * HW + r] = __ldg(&cb[d * Kv + myj]);
    }
}

extern "C" void kernel_launch(void* const* d_in, const int* in_sizes, int n_in,
                              void* d_out, int out_size) {
    const float* enc = (const float*)d_in[0];   // [32,64,64,64]
    const float* cb  = (const float*)d_in[1];   // [64,512]
    float* out = (float*)d_out;

    cudaFuncSetAttribute(vq_mma_kernel, cudaFuncAttributeMaxDynamicSharedMemorySize, SMTOT);

    split_cb_kernel<<<1, 512>>>(cb);
    const long long n_rows = (long long)out_size / Dv;    // 131072
    const int blocks = (int)(n_rows / MB);                // 1024
    vq_mma_kernel<<<blocks, THREADS, SMTOT>>>(enc, cb, out);
}

// round 15
// speedup vs baseline: 1.2129x; 1.1526x over previous
#include <cuda_runtime.h>
#include <cuda_fp16.h>
#include <cstdint>

// VectorQuantizer via mma.sync.m16n8k16 fp16 3-term split (emulated fp32 GEMM):
// x' = x*2^10 = h1+h2 (fp16), e' = e*2^14 = g1+g2 (fp16);
// mm*2^24 = h1g1 + h1g2 + h2g1 accumulated in fp32.
// R15: 4 blocks/SM (32 warps) via NCH=32 (acc 16 regs), launch_bounds(256,4),
// smem 52.2KB; parallel split_cb. Candidate distances bit-identical to R14.
// encodings [32,64,64,64] f32 (B,D,H,W), codebook [64,512] f32.

#define Dv 64
#define Kv 512
#define HW 4096
#define MB 128
#define THREADS 256
#define NCH 32                  // codewords per chunk
#define NCHUNKS (Kv / NCH)      // 16

#define XSCALE 1024.0f          // 2^10
#define ESCALE 16384.0f         // 2^14
#define INVSC2 1.1920928955078125e-7f   // 2^-23, exact: fl(acc*2^-23) == 2*fl(acc*2^-24)

// ---- smem layout (bytes) ----
#define SA      0               // 2 x [128 rows][128B] fp16 A splits (swizzled)
#define SBB(p)  (32768 + (p) * 8192)    // 2 x (2 x [32 rows][128B]) B splits
#define SEE     49152           // f32[512]
#define SXX     51200           // f32[128]
#define SBJ     51712           // i32[128]
#define SMTOT   52224

__device__ unsigned g_pack[2][Kv * 32];   // fp16 pairs, [split][j][d2], k-major
__device__ float    g_ee[Kv];

__device__ __forceinline__ void split2(float v, unsigned short& a, unsigned short& b) {
    __half h1 = __float2half_rn(v);
    float r1 = v - __half2float(h1);
    __half h2 = __float2half_rn(r1);
    a = __half_as_ushort(h1);
    b = __half_as_ushort(h2);
}

// ---- kernel 1: split codebook (scaled) + codeword norms (unscaled) ----
// 8 blocks x 64 threads; per-thread computation identical to the validated
// single-block version (sequential-d fmaf ee channel preserved).
__global__ void __launch_bounds__(64) split_cb_kernel(const float* __restrict__ cb) {
    int j = blockIdx.x * 64 + threadIdx.x;
    float e = 0.0f;
#pragma unroll 4
    for (int d2 = 0; d2 < 32; d2++) {
        float c0 = cb[(2 * d2 + 0) * Kv + j];
        float c1 = cb[(2 * d2 + 1) * Kv + j];
        e = fmaf(c0, c0, e);
        e = fmaf(c1, c1, e);                 // sequential-d: validated ee channel
        unsigned short a0, b0, a1, b1;
        split2(c0 * ESCALE, a0, b0);         // exact power-of-2 scale
        split2(c1 * ESCALE, a1, b1);
        g_pack[0][j * 32 + d2] = (unsigned)a0 | ((unsigned)a1 << 16);
        g_pack[1][j * 32 + d2] = (unsigned)b0 | ((unsigned)b1 << 16);
    }
    g_ee[j] = e;
}

#define LDSM_X4(R, addr)                                                     \
    asm volatile("ldmatrix.sync.aligned.m8n8.x4.shared.b16 {%0,%1,%2,%3}, [%4];" \
                 : "=r"((R)[0]), "=r"((R)[1]), "=r"((R)[2]), "=r"((R)[3])    \
                 : "r"(addr))
#define MMA(C, A, B)                                                         \
    asm volatile("mma.sync.aligned.m16n8k16.row.col.f32.f16.f16.f32 "        \
                 "{%0,%1,%2,%3},{%4,%5,%6,%7},{%8,%9},{%0,%1,%2,%3};"        \
                 : "+f"((C)[0]), "+f"((C)[1]), "+f"((C)[2]), "+f"((C)[3])    \
                 : "r"((A)[0]), "r"((A)[1]), "r"((A)[2]), "r"((A)[3]),       \
                   "r"((B)[0]), "r"((B)[1]))

__device__ __forceinline__ void cp_async16(unsigned saddr, const void* gptr) {
    unsigned long long g = (unsigned long long)__cvta_generic_to_global((void*)gptr);
    asm volatile("cp.async.cg.shared.global [%0], [%1], 16;" :: "r"(saddr), "l"(g));
}
#define CP_COMMIT() asm volatile("cp.async.commit_group;")
#define CP_WAIT1()  asm volatile("cp.async.wait_group 1;")
#define CP_WAIT0()  asm volatile("cp.async.wait_group 0;")

extern __shared__ char smem[];

// Issue cp.async for one B chunk into buffer p (512 x 16B; 2 per thread).
__device__ __forceinline__ void stage_b_async(unsigned sb, int ch, int p, int tid) {
#pragma unroll
    for (int it = 0; it < 2; it++) {
        int i = it * THREADS + tid;
        int s = i >> 8, r = i & 255;
        int jl = r >> 3, g = r & 7;
        unsigned dst = sb + SBB(p) + s * 4096 + jl * 128
                     + (((g ^ (jl & 7)) & 7) << 4);
        cp_async16(dst, &g_pack[s][(ch * NCH + jl) * 32 + g * 4]);
    }
    CP_COMMIT();
}

// ---- kernel 2: fused split-GEMM + argmin + gather ----
__global__ void __launch_bounds__(THREADS, 4)
vq_mma_kernel(const float* __restrict__ enc, const float* __restrict__ cb,
              float* __restrict__ out) {
    unsigned sb;
    asm("{ .reg .u64 t; cvta.to.shared.u64 t, %1; cvt.u32.u64 %0, t; }"
        : "=r"(sb) : "l"(smem));
    const int tid  = threadIdx.x;
    const int wid  = tid >> 5;
    const int lane = tid & 31;

    const long long row0 = (long long)blockIdx.x * MB;
    const int b   = (int)(row0 >> 12);
    const int hw0 = (int)(row0 & 4095);
    const float* encb = enc + (long long)b * (Dv * HW) + hw0;

    float* eesh = (float*)(smem + SEE);
    float* xxsh = (float*)(smem + SXX);
    int*   bjsh = (int*)(smem + SBJ);

    // ---- kick off B chunk 0 copy immediately ----
    stage_b_async(sb, 0, 0, tid);

    // ---- stage A: split scaled x tile into 2 swizzled fp16 tiles [128][64] ----
    for (int i = tid; i < 32 * MB; i += THREADS) {
        int d2 = i >> 7, m = i & 127;
        float v0 = encb[(2 * d2 + 0) * HW + m] * XSCALE;
        float v1 = encb[(2 * d2 + 1) * HW + m] * XSCALE;
        unsigned short a0, b0, a1, b1;
        split2(v0, a0, b0);
        split2(v1, a1, b1);
        unsigned off = (unsigned)(m * 128 + (((d2 >> 2) ^ (m & 7)) << 4) + ((d2 & 3) << 2));
        *(unsigned*)(smem + SA +     0 + off) = (unsigned)a0 | ((unsigned)a1 << 16);
        *(unsigned*)(smem + SA + 16384 + off) = (unsigned)b0 | ((unsigned)b1 << 16);
    }
    eesh[tid]       = g_ee[tid];
    eesh[tid + 256] = g_ee[tid + 256];
    if (tid < MB) {      // row norms, sequential-d fmaf (validated channel), unscaled
        float v = 0.0f;
#pragma unroll 8
        for (int d = 0; d < Dv; d++) { float a = encb[d * HW + tid]; v = fmaf(a, a, v); }
        xxsh[tid] = v;
    }
    __syncthreads();

    const int r0 = lane >> 2;         // 0..7 (row within half-stripe)
    const int wr = wid * 16;          // warp row base within block

    const int rowA = wr + (lane & 15);       // warp's own 16-row stripe
    const int tA   = lane >> 4;
    const float xx0 = xxsh[wr + r0];
    const float xx1 = xxsh[wr + r0 + 8];

    float best0 = 3.4028235e38f, best1 = 3.4028235e38f;
    int   bj0 = 0, bj1 = 0;

    // B x4 lane geometry: lanes 0-15 -> n-tile 2*ntp, 16-31 -> 2*ntp+1
    const int rBbase = (lane >> 4) * 8 + (lane & 7);
    const int tB     = (lane >> 3) & 1;

    for (int ch = 0; ch < NCHUNKS; ch++) {
        __syncthreads();   // all warps done reading the buffer being overwritten
        if (ch + 1 < NCHUNKS) {
            stage_b_async(sb, ch + 1, (ch + 1) & 1, tid);
            CP_WAIT1();    // chunk ch's group complete
        } else {
            CP_WAIT0();
        }
        __syncthreads();   // chunk ch data visible to all warps

        const unsigned bbuf = sb + SBB(ch & 1);

        float acc[4][4];
#pragma unroll
        for (int nt = 0; nt < 4; nt++)
#pragma unroll
            for (int q = 0; q < 4; q++) acc[nt][q] = 0.0f;

#pragma unroll
        for (int ks = 0; ks < 4; ks++) {
            // A fragments loaded per ks (keeps live set small)
            unsigned a[2][4];
            const unsigned chA = (unsigned)(ks * 2 + tA);
#pragma unroll
            for (int s = 0; s < 2; s++) {
                unsigned addrA = sb + SA + s * 16384 + rowA * 128
                               + (((chA ^ (rowA & 7)) & 7) << 4);
                LDSM_X4(a[s], addrA);
            }
            const unsigned chB = (unsigned)(ks * 2 + tB);
#pragma unroll
            for (int ntp = 0; ntp < 2; ntp++) {
                const int rB = ntp * 16 + rBbase;
                unsigned bb[2][4];
#pragma unroll
                for (int s = 0; s < 2; s++) {
                    unsigned addrB = bbuf + s * 4096 + rB * 128
                                   + (((chB ^ (rB & 7)) & 7) << 4);
                    LDSM_X4(bb[s], addrB);
                }
#pragma unroll
                for (int u = 0; u < 2; u++) {
                    const int nt = 2 * ntp + u;
                    MMA(acc[nt], a[0], bb[0] + 2 * u);   // h1g1
                    MMA(acc[nt], a[0], bb[1] + 2 * u);   // h1g2
                    MMA(acc[nt], a[1], bb[0] + 2 * u);   // h2g1
                }
            }
        }

        // ---- fold chunk into running argmin ----
        // t = fl(acc*2^-23) == fl(2*fl(acc*2^-24)) exactly; dist = fl(fl(xx-t)+ee)
        const int nb = ch * NCH + (lane & 3) * 2;
#pragma unroll
        for (int nt = 0; nt < 4; nt++) {
            const int n0 = nb + nt * 8;
            const float e0 = eesh[n0], e1 = eesh[n0 + 1];
            float t00 = __fmul_rn(acc[nt][0], INVSC2);
            float t01 = __fmul_rn(acc[nt][1], INVSC2);
            float t10 = __fmul_rn(acc[nt][2], INVSC2);
            float t11 = __fmul_rn(acc[nt][3], INVSC2);
            float d00 = __fadd_rn(__fsub_rn(xx0, t00), e0);
            float d01 = __fadd_rn(__fsub_rn(xx0, t01), e1);
            float d10 = __fadd_rn(__fsub_rn(xx1, t10), e0);
            float d11 = __fadd_rn(__fsub_rn(xx1, t11), e1);
            if (d00 < best0) { best0 = d00; bj0 = n0; }
            if (d01 < best0) { best0 = d01; bj0 = n0 + 1; }
            if (d10 < best1) { best1 = d10; bj1 = n0; }
            if (d11 < best1) { best1 = d11; bj1 = n0 + 1; }
        }
    }

    // ---- reduce argmin within each quad of lanes sharing a row ----
#pragma unroll
    for (int off = 1; off < 4; off <<= 1) {
        float od0 = __shfl_xor_sync(0xffffffffu, best0, off);
        int   oj0 = __shfl_xor_sync(0xffffffffu, bj0,   off);
        float od1 = __shfl_xor_sync(0xffffffffu, best1, off);
        int   oj1 = __shfl_xor_sync(0xffffffffu, bj1,   off);
        if (od0 < best0 || (od0 == best0 && oj0 < bj0)) { best0 = od0; bj0 = oj0; }
        if (od1 < best1 || (od1 == best1 && oj1 < bj1)) { best1 = od1; bj1 = oj1; }
    }
    if ((lane & 3) == 0) {
        bjsh[wr + r0]     = bj0;
        bjsh[wr + r0 + 8] = bj1;
    }
    __syncthreads();

    // ---- gather winning codeword, write [B,D,H,W] coalesced ----
    {
        float* outb = out + (long long)b * (Dv * HW) + hw0;
        const int r  = tid & 127;
        const int d0 = (tid >> 7) * 32;
        const int myj = bjsh[r];
#pragma unroll 8
        for (int d = d0; d < d0 + 32; d++)
            outb[d * HW + r] = __ldg(&cb[d * Kv + myj]);
    }
}

extern "C" void kernel_launch(void* const* d_in, const int* in_sizes, int n_in,
                              void* d_out, int out_size) {
    const float* enc = (const float*)d_in[0];   // [32,64,64,64]
    const float* cb  = (const float*)d_in[1];   // [64,512]
    float* out = (float*)d_out;

    cudaFuncSetAttribute(vq_mma_kernel, cudaFuncAttributeMaxDynamicSharedMemorySize, SMTOT);

    split_cb_kernel<<<8, 64>>>(cb);
    const long long n_rows = (long long)out_size / Dv;    // 131072
    const int blocks = (int)(n_rows / MB);                // 1024
    vq_mma_kernel<<<blocks, THREADS, SMTOT>>>(enc, cb, out);
}

// round 16
// speedup vs baseline: 1.2973x; 1.0696x over previous
#include <cuda_runtime.h>
#include <cuda_fp16.h>
#include <cstdint>

// VectorQuantizer via mma.sync.m16n8k16 fp16 3-term split (emulated fp32 GEMM):
// x' = x*2^10 = h1+h2 (fp16), e' = e*2^14 = g1+g2 (fp16);
// mm*2^24 = h1g1 + h1g2 + h2g1 accumulated in fp32.
// R16: B operand pre-arranged in gmem in exact mma fragment layout; main loop
// loads B via coalesced __ldg uint4 -> NO barriers / cp.async / smem-B at all.
// A stays in smem (LDSM per ks). 4 blocks/SM, 32 warps.
// encodings [32,64,64,64] f32 (B,D,H,W), codebook [64,512] f32.

#define Dv 64
#define Kv 512
#define HW 4096
#define MB 128
#define THREADS 256
#define NCH 32                  // codewords per chunk
#define NCHUNKS (Kv / NCH)      // 16

#define XSCALE 1024.0f          // 2^10
#define ESCALE 16384.0f         // 2^14
#define INVSC2 1.1920928955078125e-7f   // 2^-23, exact: fl(acc*2^-23) == 2*fl(acc*2^-24)

// ---- smem layout (bytes) ----
#define SA      0               // 2 x [128 rows][128B] fp16 A splits (swizzled)
#define SEE     32768           // f32[512]
#define SXX     34816           // f32[128]
#define SBJ     35328           // i32[128]
#define SMTOT   35840

// B fragments in gmem, mma-ready: index = ((ch*4+ks)*2+s)*64 + ntp*32 + lane
// uint4 = { u0.b0, u0.b1, u1.b0, u1.b1 } fp16x2 regs for cw-tile ntp, chunk ch.
__device__ uint4 g_frag[NCHUNKS * 4 * 2 * 2 * 32];   // 8192 x 16B = 128KB
__device__ float g_ee[Kv];

__device__ __forceinline__ void split2(float v, unsigned short& a, unsigned short& b) {
    __half h1 = __float2half_rn(v);
    float r1 = v - __half2float(h1);
    __half h2 = __float2half_rn(r1);
    a = __half_as_ushort(h1);
    b = __half_as_ushort(h2);
}

// ---- kernel 1: emit codebook splits in B-fragment layout + codeword norms ----
__global__ void __launch_bounds__(256) split_cb_kernel(const float* __restrict__ cb) {
    int i = blockIdx.x * 256 + threadIdx.x;       // uint4 index, 0..8191
    int ch  = i >> 9;
    int ks  = (i >> 7) & 3;
    int s   = (i >> 6) & 1;
    int ntp = (i >> 5) & 1;
    int L   = i & 31;
    int kbase = ks * 16 + (L & 3) * 2;

    unsigned vals[4];
#pragma unroll
    for (int u = 0; u < 2; u++) {
        int cw = ch * NCH + ntp * 16 + u * 8 + (L >> 2);
#pragma unroll
        for (int h = 0; h < 2; h++) {             // h=0: k-low pair, h=1: k+8 pair
            int d0 = kbase + h * 8;
            float v0 = cb[(d0 + 0) * Kv + cw] * ESCALE;   // exact 2^14 scale
            float v1 = cb[(d0 + 1) * Kv + cw] * ESCALE;
            unsigned short p0, q0, p1, q1;
            split2(v0, p0, q0);
            split2(v1, p1, q1);
            unsigned short lo = s ? q0 : p0;
            unsigned short hi = s ? q1 : p1;
            vals[u * 2 + h] = (unsigned)lo | ((unsigned)hi << 16);
        }
    }
    g_frag[i] = make_uint4(vals[0], vals[1], vals[2], vals[3]);

    // codeword norms: validated sequential-d fmaf channel
    if (i < Kv) {
        float e = 0.0f;
#pragma unroll 8
        for (int d = 0; d < Dv; d++) { float c = cb[d * Kv + i]; e = fmaf(c, c, e); }
        g_ee[i] = e;
    }
}

#define LDSM_X4(R, addr)                                                     \
    asm volatile("ldmatrix.sync.aligned.m8n8.x4.shared.b16 {%0,%1,%2,%3}, [%4];" \
                 : "=r"((R)[0]), "=r"((R)[1]), "=r"((R)[2]), "=r"((R)[3])    \
                 : "r"(addr))
#define MMA(C, A, B)                                                         \
    asm volatile("mma.sync.aligned.m16n8k16.row.col.f32.f16.f16.f32 "        \
                 "{%0,%1,%2,%3},{%4,%5,%6,%7},{%8,%9},{%0,%1,%2,%3};"        \
                 : "+f"((C)[0]), "+f"((C)[1]), "+f"((C)[2]), "+f"((C)[3])    \
                 : "r"((A)[0]), "r"((A)[1]), "r"((A)[2]), "r"((A)[3]),       \
                   "r"((B)[0]), "r"((B)[1]))

extern __shared__ char smem[];

// ---- kernel 2: fused split-GEMM + argmin + gather ----
__global__ void __launch_bounds__(THREADS, 4)
vq_mma_kernel(const float* __restrict__ enc, const float* __restrict__ cb,
              float* __restrict__ out) {
    unsigned sb;
    asm("{ .reg .u64 t; cvta.to.shared.u64 t, %1; cvt.u32.u64 %0, t; }"
        : "=r"(sb) : "l"(smem));
    const int tid  = threadIdx.x;
    const int wid  = tid >> 5;
    const int lane = tid & 31;

    const long long row0 = (long long)blockIdx.x * MB;
    const int b   = (int)(row0 >> 12);
    const int hw0 = (int)(row0 & 4095);
    const float* encb = enc + (long long)b * (Dv * HW) + hw0;

    float* eesh = (float*)(smem + SEE);
    float* xxsh = (float*)(smem + SXX);
    int*   bjsh = (int*)(smem + SBJ);

    // ---- stage A: split scaled x tile into 2 swizzled fp16 tiles [128][64] ----
    for (int i = tid; i < 32 * MB; i += THREADS) {
        int d2 = i >> 7, m = i & 127;
        float v0 = encb[(2 * d2 + 0) * HW + m] * XSCALE;
        float v1 = encb[(2 * d2 + 1) * HW + m] * XSCALE;
        unsigned short a0, b0, a1, b1;
        split2(v0, a0, b0);
        split2(v1, a1, b1);
        unsigned off = (unsigned)(m * 128 + (((d2 >> 2) ^ (m & 7)) << 4) + ((d2 & 3) << 2));
        *(unsigned*)(smem + SA +     0 + off) = (unsigned)a0 | ((unsigned)a1 << 16);
        *(unsigned*)(smem + SA + 16384 + off) = (unsigned)b0 | ((unsigned)b1 << 16);
    }
    eesh[tid]       = g_ee[tid];
    eesh[tid + 256] = g_ee[tid + 256];
    if (tid < MB) {      // row norms, sequential-d fmaf (validated channel), unscaled
        float v = 0.0f;
#pragma unroll 8
        for (int d = 0; d < Dv; d++) { float a = encb[d * HW + tid]; v = fmaf(a, a, v); }
        xxsh[tid] = v;
    }
    __syncthreads();     // the ONLY pre-epilogue barrier

    const int r0 = lane >> 2;         // 0..7 (row within half-stripe)
    const int wr = wid * 16;          // warp row base within block

    const int rowA = wr + (lane & 15);       // warp's own 16-row stripe
    const int tA   = lane >> 4;
    const float xx0 = xxsh[wr + r0];
    const float xx1 = xxsh[wr + r0 + 8];

    float best0 = 3.4028235e38f, best1 = 3.4028235e38f;
    int   bj0 = 0, bj1 = 0;

    for (int ch = 0; ch < NCHUNKS; ch++) {
        float acc[4][4];
#pragma unroll
        for (int nt = 0; nt < 4; nt++)
#pragma unroll
            for (int q = 0; q < 4; q++) acc[nt][q] = 0.0f;

        const uint4* gb = g_frag + ch * 512 + lane;   // (ch,ks) stride 128 uint4

#pragma unroll
        for (int ks = 0; ks < 4; ks++) {
            // A fragments from smem (per ks; A is read-only after staging)
            unsigned a[2][4];
            const unsigned chA = (unsigned)(ks * 2 + tA);
#pragma unroll
            for (int s = 0; s < 2; s++) {
                unsigned addrA = sb + SA + s * 16384 + rowA * 128
                               + (((chA ^ (rowA & 7)) & 7) << 4);
                LDSM_X4(a[s], addrA);
            }
            // B fragments straight from gmem (coalesced, L1/L2-hot)
            uint4 q00 = __ldg(gb + ks * 128 +  0);   // s0 ntp0
            uint4 q01 = __ldg(gb + ks * 128 + 32);   // s0 ntp1
            uint4 q10 = __ldg(gb + ks * 128 + 64);   // s1 ntp0
            uint4 q11 = __ldg(gb + ks * 128 + 96);   // s1 ntp1
            unsigned b00[4] = {q00.x, q00.y, q00.z, q00.w};
            unsigned b01[4] = {q01.x, q01.y, q01.z, q01.w};
            unsigned b10[4] = {q10.x, q10.y, q10.z, q10.w};
            unsigned b11[4] = {q11.x, q11.y, q11.z, q11.w};
#pragma unroll
            for (int u = 0; u < 2; u++) {
                MMA(acc[0 + u], a[0], b00 + 2 * u);   // h1g1 ntp0
                MMA(acc[0 + u], a[0], b10 + 2 * u);   // h1g2 ntp0
                MMA(acc[0 + u], a[1], b00 + 2 * u);   // h2g1 ntp0
                MMA(acc[2 + u], a[0], b01 + 2 * u);   // h1g1 ntp1
                MMA(acc[2 + u], a[0], b11 + 2 * u);   // h1g2 ntp1
                MMA(acc[2 + u], a[1], b01 + 2 * u);   // h2g1 ntp1
            }
        }

        // ---- fold chunk into running argmin ----
        // t = fl(acc*2^-23) == fl(2*fl(acc*2^-24)) exactly; dist = fl(fl(xx-t)+ee)
        const int nb = ch * NCH + (lane & 3) * 2;
#pragma unroll
        for (int nt = 0; nt < 4; nt++) {
            const int n0 = nb + nt * 8;
            const float e0 = eesh[n0], e1 = eesh[n0 + 1];
            float t00 = __fmul_rn(acc[nt][0], INVSC2);
            float t01 = __fmul_rn(acc[nt][1], INVSC2);
            float t10 = __fmul_rn(acc[nt][2], INVSC2);
            float t11 = __fmul_rn(acc[nt][3], INVSC2);
            float d00 = __fadd_rn(__fsub_rn(xx0, t00), e0);
            float d01 = __fadd_rn(__fsub_rn(xx0, t01), e1);
            float d10 = __fadd_rn(__fsub_rn(xx1, t10), e0);
            float d11 = __fadd_rn(__fsub_rn(xx1, t11), e1);
            if (d00 < best0) { best0 = d00; bj0 = n0; }
            if (d01 < best0) { best0 = d01; bj0 = n0 + 1; }
            if (d10 < best1) { best1 = d10; bj1 = n0; }
            if (d11 < best1) { best1 = d11; bj1 = n0 + 1; }
        }
    }

    // ---- reduce argmin within each quad of lanes sharing a row ----
#pragma unroll
    for (int off = 1; off < 4; off <<= 1) {
        float od0 = __shfl_xor_sync(0xffffffffu, best0, off);
        int   oj0 = __shfl_xor_sync(0xffffffffu, bj0,   off);
        float od1 = __shfl_xor_sync(0xffffffffu, best1, off);
        int   oj1 = __shfl_xor_sync(0xffffffffu, bj1,   off);
        if (od0 < best0 || (od0 == best0 && oj0 < bj0)) { best0 = od0; bj0 = oj0; }
        if (od1 < best1 || (od1 == best1 && oj1 < bj1)) { best1 = od1; bj1 = oj1; }
    }
    if ((lane & 3) == 0) {
        bjsh[wr + r0]     = bj0;
        bjsh[wr + r0 + 8] = bj1;
    }
    __syncthreads();

    // ---- gather winning codeword, write [B,D,H,W] coalesced ----
    {
        float* outb = out + (long long)b * (Dv * HW) + hw0;
        const int r  = tid & 127;
        const int d0 = (tid >> 7) * 32;
        const int myj = bjsh[r];
#pragma unroll 8
        for (int d = d0; d < d0 + 32; d++)
            outb[d * HW + r] = __ldg(&cb[d * Kv + myj]);
    }
}

extern "C" void kernel_launch(void* const* d_in, const int* in_sizes, int n_in,
                              void* d_out, int out_size) {
    const float* enc = (const float*)d_in[0];   // [32,64,64,64]
    const float* cb  = (const float*)d_in[1];   // [64,512]
    float* out = (float*)d_out;

    cudaFuncSetAttribute(vq_mma_kernel, cudaFuncAttributeMaxDynamicSharedMemorySize, SMTOT);

    split_cb_kernel<<<32, 256>>>(cb);
    const long long n_rows = (long long)out_size / Dv;    // 131072
    const int blocks = (int)(n_rows / MB);                // 1024
    vq_mma_kernel<<<blocks, THREADS, SMTOT>>>(enc, cb, out);
}